// round 17
// baseline (speedup 1.0000x reference)
#include <cuda_runtime.h>
#include <cuda_fp16.h>
#include <math.h>
#include <stdint.h>

// ---------------- problem constants ----------------
#define N_TOK 32768
#define HDIM  1152
#define LIGHT 1152
#define HEAVY 4608

#define NSLAB (N_TOK / 128)          // 256 row slabs
#define NCONV 64                     // fc2-weight conversion tiles
#define FC1_T (45 * NSLAB)           // 11520 fc1 tiles (9 light + 36 heavy cols)
#define FC2_T (9 * NSLAB)            // 2304 fc2 tiles
#define TOTAL_T (NCONV + FC1_T + FC2_T)

// ---------------- static scratch ----------------
__device__ __half g_hl [(size_t)N_TOK * LIGHT];
__device__ __half g_hh [(size_t)N_TOK * HEAVY];
__device__ __half g_xh [(size_t)N_TOK * HDIM];
__device__ __half g_lw1h[(size_t)LIGHT * HDIM];
__device__ __half g_hw1h[(size_t)HEAVY * HDIM];
__device__ __half g_lw2h[(size_t)HDIM * LIGHT];
__device__ __half g_hw2h[(size_t)HDIM * HEAVY];
__device__ float  g_probs[2 * N_TOK];

// scheduler state
__device__ int g_ctr;
__device__ int g_conv_done;
__device__ int g_slab_done[NSLAB];

__device__ __forceinline__ uint32_t smem_u32(const void* p) {
    uint32_t a;
    asm("{ .reg .u64 t; cvta.to.shared.u64 t, %1; cvt.u32.u64 %0, t; }" : "=r"(a) : "l"(p));
    return a;
}
__device__ __forceinline__ void cp_async16(uint32_t s, const void* g) {
    size_t gp = __cvta_generic_to_global(g);
    asm volatile("cp.async.cg.shared.global [%0], [%1], 16;" :: "r"(s), "l"(gp) : "memory");
}
#define CP_COMMIT() asm volatile("cp.async.commit_group;" ::: "memory")
#define CP_WAIT1()  asm volatile("cp.async.wait_group 1;" ::: "memory")
#define CP_WAIT0()  asm volatile("cp.async.wait_group 0;" ::: "memory")

__device__ __forceinline__ void ldmatrix_x4(uint32_t& r0, uint32_t& r1,
                                            uint32_t& r2, uint32_t& r3, uint32_t addr) {
    asm volatile("ldmatrix.sync.aligned.m8n8.x4.shared.b16 {%0,%1,%2,%3}, [%4];"
                 : "=r"(r0), "=r"(r1), "=r"(r2), "=r"(r3) : "r"(addr));
}
__device__ __forceinline__ void mma_f16(float* d, const uint32_t* a, const uint32_t* b) {
    asm volatile(
        "mma.sync.aligned.m16n8k16.row.col.f32.f16.f16.f32 "
        "{%0,%1,%2,%3}, {%4,%5,%6,%7}, {%8,%9}, {%0,%1,%2,%3};"
        : "+f"(d[0]), "+f"(d[1]), "+f"(d[2]), "+f"(d[3])
        : "r"(a[0]), "r"(a[1]), "r"(a[2]), "r"(a[3]), "r"(b[0]), "r"(b[1]));
}

__device__ __forceinline__ float gelu_fast(float v) {
    float u = 0.7978845608028654f * fmaf(0.044715f * v, v * v, v);
    float t;
    asm("tanh.approx.f32 %0, %1;" : "=f"(t) : "f"(u));
    return 0.5f * v * (1.0f + t);
}

// -------------------- scheduler reset --------------------
__global__ void reset_kernel() {
    int t = threadIdx.x;
    if (t == 0) { g_ctr = 0; g_conv_done = 0; }
    if (t < NSLAB) g_slab_done[t] = 0;
}

// -------------------- prologue: router + w1 conversions --------------------
__global__ void prologue_kernel(const float* __restrict__ x,
                                const float* __restrict__ rw,
                                const float* __restrict__ rb,
                                float* __restrict__ probs,
                                __half* __restrict__ xh,
                                const float* __restrict__ s0, __half* __restrict__ d0, int n0,
                                const float* __restrict__ s1, __half* __restrict__ d1, int n1) {
    const int ROUTER_BLOCKS = N_TOK / 8;
    if ((int)blockIdx.x >= ROUTER_BLOCKS) {
        int i = ((int)blockIdx.x - ROUTER_BLOCKS) * 256 + threadIdx.x;
        const float* s; __half* d;
        if (i < n0) { s = s0; d = d0; }
        else if ((i -= n0) < n1) { s = s1; d = d1; }
        else return;
        float4 v = ((const float4*)s)[i];
        ((__half2*)d)[2 * i]     = __floats2half2_rn(v.x, v.y);
        ((__half2*)d)[2 * i + 1] = __floats2half2_rn(v.z, v.w);
        return;
    }
    int warp = (blockIdx.x * blockDim.x + threadIdx.x) >> 5;
    int lane = threadIdx.x & 31;
    const float* xp = x + (size_t)warp * HDIM;
    __half* xo = xh + (size_t)warp * HDIM;
    float a0 = 0.f, a1 = 0.f;
    #pragma unroll
    for (int it = 0; it < HDIM / 128; it++) {
        int h = it * 128 + lane * 4;
        float4 v  = *(const float4*)(xp + h);
        float4 w0 = *(const float4*)(rw + h);
        float4 w1 = *(const float4*)(rw + HDIM + h);
        ((__half2*)xo)[h / 2]     = __floats2half2_rn(v.x, v.y);
        ((__half2*)xo)[h / 2 + 1] = __floats2half2_rn(v.z, v.w);
        a0 = fmaf(v.x, w0.x, fmaf(v.y, w0.y, fmaf(v.z, w0.z, fmaf(v.w, w0.w, a0))));
        a1 = fmaf(v.x, w1.x, fmaf(v.y, w1.y, fmaf(v.z, w1.z, fmaf(v.w, w1.w, a1))));
    }
    #pragma unroll
    for (int off = 16; off; off >>= 1) {
        a0 += __shfl_xor_sync(0xffffffffu, a0, off);
        a1 += __shfl_xor_sync(0xffffffffu, a1, off);
    }
    if (lane == 0) {
        a0 += rb[0];
        a1 += rb[1];
        float m = fmaxf(a0, a1);
        float e0 = __expf(a0 - m), e1 = __expf(a1 - m);
        float inv = 1.0f / (e0 + e1);
        probs[2 * warp]     = e0 * inv;
        probs[2 * warp + 1] = e1 * inv;
    }
}

// -------------------- fused persistent GEMM kernel --------------------
// Work queue: [0,NCONV) fc2-weight conversion; [NCONV, NCONV+FC1_T) fc1 tiles
// (slab-major, 45 cols: 9 light + 36 heavy); rest fc2 tiles (slab-major, 9 cols;
// spin until slab's 45 fc1 tiles + conv done).
// GEMM tile: CTA 128x128, 4 warps (2x2), warp 64x64, BK=64, 3-stage cp.async,
// deferred-tail pipelining.
#define STAGE_B 32768u
#define SMEM_BYTES (3 * 32768)

__global__ void __launch_bounds__(128, 2) fused_kernel(
    const __half* __restrict__ xh,
    const __half* __restrict__ lw1h, const __half* __restrict__ hw1h,
    const __half* __restrict__ lw2h, const __half* __restrict__ hw2h,
    __half* __restrict__ hl, __half* __restrict__ hh,
    const float* __restrict__ lb1, const float* __restrict__ hb1,
    const float* __restrict__ lb2, const float* __restrict__ hb2,
    const float* __restrict__ probs, float* __restrict__ out,
    const float* __restrict__ cs0, __half* __restrict__ cd0, int cn0,
    const float* __restrict__ cs1, __half* __restrict__ cd1, int cn1)
{
    extern __shared__ char smc[];
    const uint32_t sbase = smem_u32(smc);
    __shared__ int s_idx;
    const int tid  = threadIdx.x;
    const int wid  = tid >> 5, lane = tid & 31;
    const int wr   = wid >> 1;
    const int wn   = wid & 1;
    const int g    = lane >> 2;
    const int c    = lane & 3;

    // phase-stagger second co-resident CTA of each SM (classic bid%SMs placement)
    if ((int)blockIdx.x * 2 >= (int)gridDim.x) {
        unsigned long long t0 = clock64();
        while (clock64() - t0 < 1100ull) {}
    }

    // loop-invariant lane components
    const int lrow = tid >> 3;
    const int ls   = tid & 7;
    const uint32_t offR = (uint32_t)(lrow * 128 + ((ls ^ (lrow & 7)) * 16));
    const int arow = wr * 64 + (lane & 15);
    const int asel = lane >> 4;
    const int nrow = wn * 64 + (lane & 7) + ((lane >> 4) << 3);
    const int bsel2 = (lane >> 3) & 1;

    for (;;) {
        __syncthreads();
        if (tid == 0) s_idx = atomicAdd(&g_ctr, 1);
        __syncthreads();
        const int idx = s_idx;
        if (idx >= TOTAL_T) return;

        // ---------- conversion tile ----------
        if (idx < NCONV) {
            const int chunk = (cn0 + cn1 + NCONV - 1) / NCONV;
            int beg = idx * chunk;
            int end = beg + chunk;
            if (end > cn0 + cn1) end = cn0 + cn1;
            for (int i = beg + tid; i < end; i += 128) {
                const float* s; __half* d; int k = i;
                if (k < cn0) { s = cs0; d = cd0; }
                else { k -= cn0; s = cs1; d = cd1; }
                float4 v = ((const float4*)s)[k];
                ((__half2*)d)[2 * k]     = __floats2half2_rn(v.x, v.y);
                ((__half2*)d)[2 * k + 1] = __floats2half2_rn(v.z, v.w);
            }
            __syncthreads();
            __threadfence();
            if (tid == 0) atomicAdd(&g_conv_done, 1);
            continue;
        }

        // ---------- gemm tile setup ----------
        const bool fc2 = idx >= NCONV + FC1_T;
        int slab, colt, row0, col0, Nfeat, expert, KT;
        const __half* pa;
        const __half* pw;
        size_t rs;
        const float* bias0 = lb2;   // fc2 uses both
        __half* Ch = hl;
        if (!fc2) {
            int q = idx - NCONV;
            slab = q / 45; colt = q % 45; row0 = slab * 128;
            const __half* W;
            if (colt < 9) { W = lw1h; bias0 = lb1; Ch = hl; Nfeat = LIGHT; expert = 0; col0 = colt * 128; }
            else          { W = hw1h; bias0 = hb1; Ch = hh; Nfeat = HEAVY; expert = 1; col0 = (colt - 9) * 128; }
            pa = xh + (size_t)(row0 + lrow) * HDIM + ls * 8;
            pw = W  + (size_t)(col0 + lrow) * HDIM + ls * 8;
            rs = (size_t)16 * HDIM;
            KT = HDIM / 64;
        } else {
            int q = idx - NCONV - FC1_T;
            slab = q / 9; colt = q % 9; row0 = slab * 128; col0 = colt * 128;
            Nfeat = HDIM; expert = 0;
            pa = hl   + (size_t)(row0 + lrow) * LIGHT + ls * 8;
            pw = lw2h + (size_t)(col0 + lrow) * LIGHT + ls * 8;
            rs = (size_t)16 * LIGHT;
            KT = (LIGHT + HEAVY) / 64;  // 90
            if (tid == 0) {
                while (atomicAdd(&g_conv_done, 0) < NCONV) __nanosleep(100);
                while (atomicAdd(&g_slab_done[slab], 0) < 45) __nanosleep(100);
            }
            __syncthreads();
        }
        const int KT0 = LIGHT / 64;  // 18

        float acc[4][8][4];
        #pragma unroll
        for (int i = 0; i < 4; i++)
            #pragma unroll
            for (int j = 0; j < 8; j++)
                #pragma unroll
                for (int q2 = 0; q2 < 4; q2++) acc[i][j][q2] = 0.f;

        int issued = 0;
        uint32_t so = 0;
        auto issue_next = [&]() {
            if (fc2 && issued == KT0) {
                pa = hh   + (size_t)(row0 + lrow) * HEAVY + ls * 8;
                pw = hw2h + (size_t)(col0 + lrow) * HEAVY + ls * 8;
                rs = (size_t)16 * HEAVY;
            }
            #pragma unroll
            for (int i = 0; i < 8; i++) {
                cp_async16(sbase + so + offR + (uint32_t)i * 2048u,          pa + (size_t)i * rs);
                cp_async16(sbase + so + 16384u + offR + (uint32_t)i * 2048u, pw + (size_t)i * rs);
            }
            pa += 64; pw += 64;
            issued++;
            so += STAGE_B; if (so == 3 * STAGE_B) so = 0;
        };

        uint32_t af[2][4][4], bf[2][4][4];
        auto ldA = [&](uint32_t as, int ks, uint32_t dst[4][4]) {
            const uint32_t p = (uint32_t)((((ks * 2 + asel) ^ (arow & 7)) * 16));
            const uint32_t base = as + (uint32_t)(arow * 128) + p;
            #pragma unroll
            for (int i = 0; i < 4; i++)
                ldmatrix_x4(dst[i][0], dst[i][1], dst[i][2], dst[i][3], base + (uint32_t)(i * 2048));
        };
        auto ldB = [&](uint32_t ws, int ks, uint32_t dst[4][4]) {
            const uint32_t p = (uint32_t)((((ks * 2 + bsel2) ^ (nrow & 7)) * 16));
            const uint32_t base = ws + (uint32_t)(nrow * 128) + p;
            #pragma unroll
            for (int j2 = 0; j2 < 4; j2++)
                ldmatrix_x4(dst[j2][0], dst[j2][1], dst[j2][2], dst[j2][3], base + (uint32_t)(j2 * 2048));
        };
        auto mma_block = [&](int buf) {
            #pragma unroll
            for (int i = 0; i < 4; i++)
                #pragma unroll
                for (int j = 0; j < 8; j++)
                    mma_f16(acc[i][j], af[buf][i], &bf[buf][j >> 1][(j & 1) * 2]);
        };
        auto compute_head = [&](uint32_t co) {
            const uint32_t as = sbase + co;
            const uint32_t ws = as + 16384u;
            ldB(ws, 0, bf[0]);
            ldA(as, 0, af[0]);
            #pragma unroll
            for (int ks = 0; ks < 3; ks++) {
                const int cur = ks & 1;
                ldB(ws, ks + 1, bf[cur ^ 1]);
                ldA(as, ks + 1, af[cur ^ 1]);
                mma_block(cur);
            }
        };

        issue_next(); CP_COMMIT();
        issue_next(); CP_COMMIT();
        uint32_t co = 0;

        CP_WAIT1();
        __syncthreads();
        if (KT > 2) issue_next();
        CP_COMMIT();
        compute_head(co);
        co += STAGE_B; if (co == 3 * STAGE_B) co = 0;

        for (int kt = 1; kt < KT; kt++) {
            mma_block(1);
            CP_WAIT1();
            __syncthreads();
            if (kt + 2 < KT) issue_next();
            CP_COMMIT();
            compute_head(co);
            co += STAGE_B; if (co == 3 * STAGE_B) co = 0;
        }
        mma_block(1);
        CP_WAIT0();

        // ---------- epilogue ----------
        #pragma unroll
        for (int i = 0; i < 4; i++) {
            const int rowA = row0 + wr * 64 + i * 16 + g;
            float p0a, p1a, p0b, p1b;
            if (!fc2) {
                p0a = probs[2 * rowA + expert];
                p0b = probs[2 * (rowA + 8) + expert];
                p1a = p1b = 0.f;
            } else {
                p0a = probs[2 * rowA];       p1a = probs[2 * rowA + 1];
                p0b = probs[2 * (rowA + 8)]; p1b = probs[2 * (rowA + 8) + 1];
            }
            #pragma unroll
            for (int j = 0; j < 8; j++) {
                const int col = col0 + wn * 64 + j * 8 + c * 2;
                if (!fc2) {
                    const float b0 = bias0[col], b1 = bias0[col + 1];
                    __half* o0 = Ch + (size_t)rowA * Nfeat + col;
                    __half* o1 = Ch + (size_t)(rowA + 8) * Nfeat + col;
                    *(__half2*)o0 = __floats2half2_rn(p0a * gelu_fast(acc[i][j][0] + b0),
                                                      p0a * gelu_fast(acc[i][j][1] + b1));
                    *(__half2*)o1 = __floats2half2_rn(p0b * gelu_fast(acc[i][j][2] + b0),
                                                      p0b * gelu_fast(acc[i][j][3] + b1));
                } else {
                    const float bl0 = lb2[col], bl1 = lb2[col + 1];
                    const float bh0 = hb2[col], bh1 = hb2[col + 1];
                    float* o0 = out + (size_t)rowA * HDIM + col;
                    float* o1 = out + (size_t)(rowA + 8) * HDIM + col;
                    o0[0] = acc[i][j][0] + p0a * bl0 + p1a * bh0;
                    o0[1] = acc[i][j][1] + p0a * bl1 + p1a * bh1;
                    o1[0] = acc[i][j][2] + p0b * bl0 + p1b * bh0;
                    o1[1] = acc[i][j][3] + p0b * bl1 + p1b * bh1;
                }
            }
        }

        if (!fc2) {
            __syncthreads();
            __threadfence();
            if (tid == 0) atomicAdd(&g_slab_done[slab], 1);
        }
    }
}

// -------------------- launch --------------------
extern "C" void kernel_launch(void* const* d_in, const int* in_sizes, int n_in,
                              void* d_out, int out_size) {
    const float* x        = (const float*)d_in[0];
    const float* router_w = (const float*)d_in[1];
    const float* router_b = (const float*)d_in[2];
    const float* light_w1 = (const float*)d_in[3];
    const float* light_b1 = (const float*)d_in[4];
    const float* light_w2 = (const float*)d_in[5];
    const float* light_b2 = (const float*)d_in[6];
    const float* heavy_w1 = (const float*)d_in[7];
    const float* heavy_b1 = (const float*)d_in[8];
    const float* heavy_w2 = (const float*)d_in[9];
    const float* heavy_b2 = (const float*)d_in[10];
    float* out = (float*)d_out;

    __half *hl, *hh, *xh, *lw1h, *hw1h, *lw2h, *hw2h;
    float* probs;
    cudaGetSymbolAddress((void**)&hl, g_hl);
    cudaGetSymbolAddress((void**)&hh, g_hh);
    cudaGetSymbolAddress((void**)&xh, g_xh);
    cudaGetSymbolAddress((void**)&lw1h, g_lw1h);
    cudaGetSymbolAddress((void**)&hw1h, g_hw1h);
    cudaGetSymbolAddress((void**)&lw2h, g_lw2h);
    cudaGetSymbolAddress((void**)&hw2h, g_hw2h);
    cudaGetSymbolAddress((void**)&probs, g_probs);

    static int nworkers = 0;
    if (nworkers == 0) {
        int sms = 148;
        cudaDeviceGetAttribute(&sms, cudaDevAttrMultiProcessorCount, 0);
        nworkers = 2 * sms;
        cudaFuncSetAttribute(fused_kernel, cudaFuncAttributeMaxDynamicSharedMemorySize, SMEM_BYTES);
    }

    reset_kernel<<<1, 256>>>();

    // prologue: router (vectorized) + w1 conversions
    {
        const int n0 = LIGHT * HDIM / 4, n1 = HEAVY * HDIM / 4;
        const int wblocks = (n0 + n1 + 255) / 256;
        prologue_kernel<<<N_TOK / 8 + wblocks, 256>>>(
            x, router_w, router_b, probs, xh,
            light_w1, lw1h, n0, heavy_w1, hw1h, n1);
    }

    // fused persistent conv(w2) + fc1 + fc2
    fused_kernel<<<nworkers, 128, SMEM_BYTES>>>(
        xh, lw1h, hw1h, lw2h, hw2h, hl, hh,
        light_b1, heavy_b1, light_b2, heavy_b2,
        probs, out,
        light_w2, lw2h, HDIM * LIGHT / 4, heavy_w2, hw2h, HDIM * HEAVY / 4);
}